// round 5
// baseline (speedup 1.0000x reference)
#include <cuda_runtime.h>
#include <cstdint>

#define NUM_A 8
#define EDIM 128
#define OUTSTRIDE (NUM_A * EDIM)   // 1024 floats per batch row of edge/out
#define KC 32                      // K elements per pipeline chunk
#define CHPT 8                     // chunks per tile (K = 256)
#define NSTAGE 3
#define MTILE 128
#define THREADS 256
#define STAGE_BYTES (2 * EDIM * KC * 4)   // A tile (16KB) + B tile (16KB) = 32KB

// Precomputed fused weights (tf32-rounded) and bias-through-projection.
__device__ float g_P1T[NUM_A * EDIM * EDIM];   // [a][j][k] = sum_i W[i,k]   * proj[a,i,j]
__device__ float g_P2T[NUM_A * EDIM * EDIM];   // [a][j][k] = sum_i W[i,E+k] * proj[a,i,j]
__device__ float g_cvec[NUM_A * EDIM];         // [a][j]    = sum_i b[i]     * proj[a,i,j]

__device__ __forceinline__ uint32_t swz(uint32_t x) { return x ^ ((x >> 3) & 0x70u); }

__device__ __forceinline__ void cp_async16(uint32_t dst, const void* src) {
    asm volatile("cp.async.cg.shared.global [%0], [%1], 16;" :: "r"(dst), "l"(src));
}
__device__ __forceinline__ void cp_commit() { asm volatile("cp.async.commit_group;"); }
template <int N> __device__ __forceinline__ void cp_wait() {
    asm volatile("cp.async.wait_group %0;" :: "n"(N));
}

__device__ __forceinline__ void ldsm_x4(uint32_t& r0, uint32_t& r1, uint32_t& r2, uint32_t& r3,
                                        uint32_t addr) {
    asm volatile("ldmatrix.sync.aligned.m8n8.x4.shared.b16 {%0,%1,%2,%3}, [%4];"
                 : "=r"(r0), "=r"(r1), "=r"(r2), "=r"(r3) : "r"(addr));
}
__device__ __forceinline__ uint32_t to_tf32(uint32_t x) {
    uint32_t y;
    asm("cvt.rna.tf32.f32 %0, %1;" : "=r"(y) : "f"(__uint_as_float(x)));
    return y;
}
__device__ __forceinline__ void mma_tf32(float* c, const uint32_t* a, uint32_t b0, uint32_t b1) {
    asm volatile("mma.sync.aligned.m16n8k8.row.col.f32.tf32.tf32.f32 "
                 "{%0,%1,%2,%3},{%4,%5,%6,%7},{%8,%9},{%0,%1,%2,%3};"
                 : "+f"(c[0]), "+f"(c[1]), "+f"(c[2]), "+f"(c[3])
                 : "r"(a[0]), "r"(a[1]), "r"(a[2]), "r"(a[3]), "r"(b0), "r"(b1));
}

// ---------------------------------------------------------------------------
// Precompute: P1T/P2T (stored j-major = n-major, tf32-rounded) and cvec.
// ---------------------------------------------------------------------------
__global__ void precompute_kernel(const float* __restrict__ W, const float* __restrict__ bvec,
                                  const float* __restrict__ proj) {
    const int a = blockIdx.x;
    const int j = blockIdx.y;
    const int k = threadIdx.x;
    const float* pa = proj + ((size_t)a * EDIM) * EDIM + j;   // proj[a][i][j], stride E
    float acc1 = 0.f, acc2 = 0.f, accC = 0.f;
#pragma unroll 8
    for (int i = 0; i < EDIM; i++) {
        float p = __ldg(pa + (size_t)i * EDIM);
        acc1 = fmaf(__ldg(W + i * 2 * EDIM + k), p, acc1);
        acc2 = fmaf(__ldg(W + i * 2 * EDIM + EDIM + k), p, acc2);
        accC = fmaf(__ldg(bvec + i), p, accC);
    }
    size_t o = ((size_t)a * EDIM + j) * EDIM + k;
    g_P1T[o] = __uint_as_float(to_tf32(__float_as_uint(acc1)));
    g_P2T[o] = __uint_as_float(to_tf32(__float_as_uint(acc2)));
    if (k == 0) g_cvec[a * EDIM + j] = accC;
}

// ---------------------------------------------------------------------------
// PERSISTENT fused GEMM. Each CTA loops over (a, m-tile) work items; the
// 3-stage cp.async ring is indexed by a global chunk counter that rolls
// continuously across tile boundaries, so DRAM cold-start is paid exactly
// once per CTA and the register epilogue (no smem, no barrier) overlaps the
// in-flight loads of the next tile. tf32 mma.sync m16n8k8, 2 CTAs/SM.
// ---------------------------------------------------------------------------
__global__ __launch_bounds__(THREADS, 2) void gnn_kernel(const float* __restrict__ img,
                                                         const float* __restrict__ edge,
                                                         float* __restrict__ out,
                                                         int num_tiles) {
    extern __shared__ float smem[];
    const uint32_t smem_b = (uint32_t)__cvta_generic_to_shared(smem);
    const int tid = threadIdx.x;
    const int lane = tid & 31;
    const int warp = tid >> 5;
    const int m0 = (warp & 3) * 32;    // warp row base within CTA tile
    const int n0 = (warp >> 2) * 64;   // warp col base within CTA tile
    const int bid = blockIdx.x;
    const int gsz = gridDim.x;

    // number of tiles this CTA owns
    int my_tiles = (num_tiles - bid + gsz - 1) / gsz;
    if (my_tiles <= 0) return;
    const int total_chunks = my_tiles * CHPT;

    float acc[2][8][4];
#pragma unroll
    for (int mt = 0; mt < 2; mt++)
#pragma unroll
        for (int nt = 0; nt < 8; nt++)
#pragma unroll
            for (int v = 0; v < 4; v++) acc[mt][nt][v] = 0.f;

    // Load chunk with global index g into stage s. tile = bid + (g/8)*gsz.
    auto load_chunk = [&](int g, int s) {
        const int tile = bid + (g >> 3) * gsz;
        const int a = tile & (NUM_A - 1);
        const int mbase = (tile >> 3) * MTILE;
        const int kc = g & 7;
        const uint32_t abase = smem_b + s * STAGE_BYTES;
        const uint32_t bbase = abase + EDIM * KC * 4;
        const float* srcAbase;
        size_t strideA;
        if (kc < 4) { srcAbase = img + (size_t)mbase * EDIM + kc * KC;                 strideA = EDIM; }
        else        { srcAbase = edge + (size_t)mbase * OUTSTRIDE + a * EDIM + (kc - 4) * KC; strideA = OUTSTRIDE; }
        const float* PT = (kc < 4) ? g_P1T : g_P2T;
        const float* srcBbase = PT + ((size_t)a * EDIM) * EDIM + (kc & 3) * KC;
#pragma unroll
        for (int q = 0; q < 4; q++) {
            int id = tid + q * THREADS;   // 0..1023
            int row = id >> 3;
            int c4 = id & 7;
            cp_async16(abase + swz((uint32_t)(row * 128 + c4 * 16)),
                       srcAbase + (size_t)row * strideA + c4 * 4);
        }
#pragma unroll
        for (int q = 0; q < 4; q++) {
            int id = tid + q * THREADS;
            int row = id >> 3;            // = j
            int c4 = id & 7;
            cp_async16(bbase + swz((uint32_t)(row * 128 + c4 * 16)),
                       srcBbase + (size_t)row * EDIM + c4 * 4);
        }
        cp_commit();
    };

    auto compute_chunk = [&](int s) {
        const uint32_t abase = smem_b + s * STAGE_BYTES;
        const uint32_t bbase = abase + EDIM * KC * 4;
#pragma unroll
        for (int ks = 0; ks < 4; ks++) {   // 4 k8 steps per 32-wide chunk
            uint32_t afr[2][4];
#pragma unroll
            for (int mt = 0; mt < 2; mt++) {
                int rowA = m0 + mt * 16 + (lane & 7) + (lane & 8);
                uint32_t kb = (uint32_t)(ks * 32 + (lane & 16));
                ldsm_x4(afr[mt][0], afr[mt][1], afr[mt][2], afr[mt][3],
                        abase + rowA * 128 + (kb ^ (uint32_t)((rowA & 7) << 4)));
            }
#pragma unroll
            for (int mt = 0; mt < 2; mt++)
#pragma unroll
                for (int v = 0; v < 4; v++) afr[mt][v] = to_tf32(afr[mt][v]);
            uint32_t bfr[4][4];
#pragma unroll
            for (int nt2 = 0; nt2 < 4; nt2++) {
                int rowB = n0 + nt2 * 16 + (lane & 7) + ((lane & 16) >> 1);
                uint32_t kb = (uint32_t)(ks * 32 + ((lane & 8) << 1));
                ldsm_x4(bfr[nt2][0], bfr[nt2][1], bfr[nt2][2], bfr[nt2][3],
                        bbase + rowB * 128 + (kb ^ (uint32_t)((rowB & 7) << 4)));
            }
#pragma unroll
            for (int mt = 0; mt < 2; mt++)
#pragma unroll
                for (int nt2 = 0; nt2 < 4; nt2++) {
                    mma_tf32(acc[mt][nt2 * 2],     afr[mt], bfr[nt2][0], bfr[nt2][1]);
                    mma_tf32(acc[mt][nt2 * 2 + 1], afr[mt], bfr[nt2][2], bfr[nt2][3]);
                }
        }
    };

    load_chunk(0, 0);
    if (total_chunks > 1) load_chunk(1, 1);

#pragma unroll 1
    for (int g = 0; g < total_chunks; g++) {
        if (g < total_chunks - 1) { cp_wait<1>(); } else { cp_wait<0>(); }
        __syncthreads();
        if (g + 2 < total_chunks) load_chunk(g + 2, (g + 2) % NSTAGE);
        compute_chunk(g % NSTAGE);

        if ((g & 7) == 7) {
            // Tile finished: register epilogue (no smem, no barrier needed).
            const int tile = bid + (g >> 3) * gsz;
            const int a = tile & (NUM_A - 1);
            const int mbase = (tile >> 3) * MTILE;
            const float* cv = g_cvec + a * EDIM;
#pragma unroll
            for (int mt = 0; mt < 2; mt++) {
                int r0 = mbase + m0 + mt * 16 + (lane >> 2);
#pragma unroll
                for (int nt = 0; nt < 8; nt++) {
                    int col = n0 + (nt >> 1) * 16 + (nt & 1) * 8 + (lane & 3) * 2;
                    float b0 = __ldg(cv + col);
                    float b1 = __ldg(cv + col + 1);
                    float2 v0 = make_float2(acc[mt][nt][0] + b0, acc[mt][nt][1] + b1);
                    float2 v1 = make_float2(acc[mt][nt][2] + b0, acc[mt][nt][3] + b1);
                    size_t base0 = (size_t)r0 * OUTSTRIDE + a * EDIM + col;
                    size_t base1 = (size_t)(r0 + 8) * OUTSTRIDE + a * EDIM + col;
                    *reinterpret_cast<float2*>(out + base0) = v0;
                    *reinterpret_cast<float2*>(out + base1) = v1;
                    acc[mt][nt][0] = 0.f; acc[mt][nt][1] = 0.f;
                    acc[mt][nt][2] = 0.f; acc[mt][nt][3] = 0.f;
                }
            }
        }
    }
}

extern "C" void kernel_launch(void* const* d_in, const int* in_sizes, int n_in,
                              void* d_out, int out_size) {
    const float* img  = (const float*)d_in[0];   // [B, E]
    const float* edge = (const float*)d_in[1];   // [B, A, E]
    const float* W    = (const float*)d_in[2];   // [E, 2E]
    const float* bvec = (const float*)d_in[3];   // [E]
    const float* proj = (const float*)d_in[4];   // [A, E, E]
    const int Bn = in_sizes[0] / EDIM;
    const int num_tiles = NUM_A * (Bn / MTILE);  // tile = (a fast, m slow)

    precompute_kernel<<<dim3(NUM_A, EDIM), EDIM>>>(W, bvec, proj);

    int sms = 148;
    cudaDeviceGetAttribute(&sms, cudaDevAttrMultiProcessorCount, 0);
    int grid = 2 * sms;
    if (grid > num_tiles) grid = num_tiles;

    cudaFuncSetAttribute(gnn_kernel, cudaFuncAttributeMaxDynamicSharedMemorySize,
                         NSTAGE * STAGE_BYTES);
    gnn_kernel<<<grid, THREADS, NSTAGE * STAGE_BYTES>>>(img, edge, (float*)d_out, num_tiles);
}

// round 6
// speedup vs baseline: 1.0500x; 1.0500x over previous
#include <cuda_runtime.h>
#include <cstdint>

#define NUM_A 8
#define EDIM 128
#define OUTSTRIDE (NUM_A * EDIM)   // 1024 floats per batch row of edge/out
#define KC 32                      // K elements per pipeline chunk
#define NCHUNK 8                   // total K = 256 (128 img + 128 edge)
#define NSTAGE 3
#define MTILE 128
#define THREADS 128                // 4 warps, each owning a 64x64 output tile
#define STAGE_BYTES (2 * EDIM * KC * 4)   // A tile (16KB) + B tile (16KB) = 32KB

// Precomputed fused weights (tf32-rounded) and bias-through-projection.
__device__ float g_P1T[NUM_A * EDIM * EDIM];   // [a][j][k] = sum_i W[i,k]   * proj[a,i,j]
__device__ float g_P2T[NUM_A * EDIM * EDIM];   // [a][j][k] = sum_i W[i,E+k] * proj[a,i,j]
__device__ float g_cvec[NUM_A * EDIM];         // [a][j]    = sum_i b[i]     * proj[a,i,j]

__device__ __forceinline__ uint32_t swz(uint32_t x) { return x ^ ((x >> 3) & 0x70u); }

__device__ __forceinline__ void cp_async16(uint32_t dst, const void* src) {
    asm volatile("cp.async.cg.shared.global [%0], [%1], 16;" :: "r"(dst), "l"(src));
}
__device__ __forceinline__ void cp_commit() { asm volatile("cp.async.commit_group;"); }
template <int N> __device__ __forceinline__ void cp_wait() {
    asm volatile("cp.async.wait_group %0;" :: "n"(N));
}

__device__ __forceinline__ void ldsm_x4(uint32_t& r0, uint32_t& r1, uint32_t& r2, uint32_t& r3,
                                        uint32_t addr) {
    asm volatile("ldmatrix.sync.aligned.m8n8.x4.shared.b16 {%0,%1,%2,%3}, [%4];"
                 : "=r"(r0), "=r"(r1), "=r"(r2), "=r"(r3) : "r"(addr));
}
__device__ __forceinline__ uint32_t to_tf32(uint32_t x) {
    uint32_t y;
    asm("cvt.rna.tf32.f32 %0, %1;" : "=r"(y) : "f"(__uint_as_float(x)));
    return y;
}
__device__ __forceinline__ void mma_tf32(float* c, const uint32_t* a, uint32_t b0, uint32_t b1) {
    asm volatile("mma.sync.aligned.m16n8k8.row.col.f32.tf32.tf32.f32 "
                 "{%0,%1,%2,%3},{%4,%5,%6,%7},{%8,%9},{%0,%1,%2,%3};"
                 : "+f"(c[0]), "+f"(c[1]), "+f"(c[2]), "+f"(c[3])
                 : "r"(a[0]), "r"(a[1]), "r"(a[2]), "r"(a[3]), "r"(b0), "r"(b1));
}

// ---------------------------------------------------------------------------
// Precompute: P1T/P2T (stored j-major = n-major, tf32-rounded) and cvec.
// ---------------------------------------------------------------------------
__global__ void precompute_kernel(const float* __restrict__ W, const float* __restrict__ bvec,
                                  const float* __restrict__ proj) {
    const int a = blockIdx.x;
    const int j = blockIdx.y;
    const int k = threadIdx.x;
    const float* pa = proj + ((size_t)a * EDIM) * EDIM + j;   // proj[a][i][j], stride E
    float acc1 = 0.f, acc2 = 0.f, accC = 0.f;
#pragma unroll 8
    for (int i = 0; i < EDIM; i++) {
        float p = __ldg(pa + (size_t)i * EDIM);
        acc1 = fmaf(__ldg(W + i * 2 * EDIM + k), p, acc1);
        acc2 = fmaf(__ldg(W + i * 2 * EDIM + EDIM + k), p, acc2);
        accC = fmaf(__ldg(bvec + i), p, accC);
    }
    size_t o = ((size_t)a * EDIM + j) * EDIM + k;
    g_P1T[o] = __uint_as_float(to_tf32(__float_as_uint(acc1)));
    g_P2T[o] = __uint_as_float(to_tf32(__float_as_uint(acc2)));
    if (k == 0) g_cvec[a * EDIM + j] = accC;
}

// ---------------------------------------------------------------------------
// Fused GEMM: CTA = (a, 128-row m-tile), 4 warps each computing 64x64.
// Warp-tile 64x64 cuts smem fragment traffic to A-tile x2 + B-tile x2 =
// 64KB reads/chunk (was 96KB with 32x64 tiles) -> crossbar no longer caps the
// tensor pipe. 32 independent HMMAs per k-step per warp for ILP. 2 CTAs/SM.
// tf32 mma.sync m16n8k8; 3-stage cp.async pipeline, one barrier per chunk.
// ---------------------------------------------------------------------------
__global__ __launch_bounds__(THREADS, 2) void gnn_kernel(const float* __restrict__ img,
                                                         const float* __restrict__ edge,
                                                         float* __restrict__ out) {
    extern __shared__ float smem[];
    const uint32_t smem_b = (uint32_t)__cvta_generic_to_shared(smem);
    const int a = blockIdx.x;
    const int mbase = blockIdx.y * MTILE;
    const int tid = threadIdx.x;
    const int lane = tid & 31;
    const int warp = tid >> 5;
    const int m0 = (warp & 1) * 64;    // warp row base within CTA tile
    const int n0 = (warp >> 1) * 64;   // warp col base within CTA tile

    float acc[4][8][4];
#pragma unroll
    for (int mt = 0; mt < 4; mt++)
#pragma unroll
        for (int nt = 0; nt < 8; nt++)
#pragma unroll
            for (int v = 0; v < 4; v++) acc[mt][nt][v] = 0.f;

    auto load_chunk = [&](int kc, int s) {
        const uint32_t abase = smem_b + s * STAGE_BYTES;
        const uint32_t bbase = abase + EDIM * KC * 4;
        const float* srcAbase;
        size_t strideA;
        if (kc < 4) { srcAbase = img + (size_t)mbase * EDIM + kc * KC;                 strideA = EDIM; }
        else        { srcAbase = edge + (size_t)mbase * OUTSTRIDE + a * EDIM + (kc - 4) * KC; strideA = OUTSTRIDE; }
        const float* PT = (kc < 4) ? g_P1T : g_P2T;
        const float* srcBbase = PT + ((size_t)a * EDIM) * EDIM + (kc & 3) * KC;
#pragma unroll
        for (int q = 0; q < 8; q++) {
            int id = tid + q * THREADS;   // 0..1023
            int row = id >> 3;
            int c4 = id & 7;
            cp_async16(abase + swz((uint32_t)(row * 128 + c4 * 16)),
                       srcAbase + (size_t)row * strideA + c4 * 4);
        }
#pragma unroll
        for (int q = 0; q < 8; q++) {
            int id = tid + q * THREADS;
            int row = id >> 3;            // = j
            int c4 = id & 7;
            cp_async16(bbase + swz((uint32_t)(row * 128 + c4 * 16)),
                       srcBbase + (size_t)row * EDIM + c4 * 4);
        }
        cp_commit();
    };

    auto compute_chunk = [&](int s) {
        const uint32_t abase = smem_b + s * STAGE_BYTES;
        const uint32_t bbase = abase + EDIM * KC * 4;
#pragma unroll
        for (int ks = 0; ks < 4; ks++) {   // 4 k8 steps per 32-wide chunk
            uint32_t afr[4][4];
#pragma unroll
            for (int mt = 0; mt < 4; mt++) {
                int rowA = m0 + mt * 16 + (lane & 7) + (lane & 8);
                uint32_t kb = (uint32_t)(ks * 32 + (lane & 16));
                ldsm_x4(afr[mt][0], afr[mt][1], afr[mt][2], afr[mt][3],
                        abase + rowA * 128 + (kb ^ (uint32_t)((rowA & 7) << 4)));
            }
#pragma unroll
            for (int mt = 0; mt < 4; mt++)
#pragma unroll
                for (int v = 0; v < 4; v++) afr[mt][v] = to_tf32(afr[mt][v]);
            uint32_t bfr[4][4];
#pragma unroll
            for (int nt2 = 0; nt2 < 4; nt2++) {
                int rowB = n0 + nt2 * 16 + (lane & 7) + ((lane & 16) >> 1);
                uint32_t kb = (uint32_t)(ks * 32 + ((lane & 8) << 1));
                ldsm_x4(bfr[nt2][0], bfr[nt2][1], bfr[nt2][2], bfr[nt2][3],
                        bbase + rowB * 128 + (kb ^ (uint32_t)((rowB & 7) << 4)));
            }
#pragma unroll
            for (int mt = 0; mt < 4; mt++)
#pragma unroll
                for (int nt2 = 0; nt2 < 4; nt2++) {
                    mma_tf32(acc[mt][nt2 * 2],     afr[mt], bfr[nt2][0], bfr[nt2][1]);
                    mma_tf32(acc[mt][nt2 * 2 + 1], afr[mt], bfr[nt2][2], bfr[nt2][3]);
                }
        }
    };

    // 3-stage pipeline: preload chunks 0,1; each iteration waits for chunk kc,
    // barriers once, issues load kc+2 into the stage freed by compute kc-1,
    // then computes kc while loads kc+1 / kc+2 are in flight.
    load_chunk(0, 0);
    load_chunk(1, 1);
#pragma unroll 1
    for (int kc = 0; kc < NCHUNK; kc++) {
        if (kc < NCHUNK - 1) { cp_wait<1>(); } else { cp_wait<0>(); }
        __syncthreads();
        if (kc + 2 < NCHUNK) load_chunk(kc + 2, (kc + 2) % NSTAGE);
        compute_chunk(kc % NSTAGE);
    }

    // Epilogue: add bias-through-projection, store float2 pairs.
    const float* cv = g_cvec + a * EDIM;
#pragma unroll
    for (int mt = 0; mt < 4; mt++) {
        int r0 = mbase + m0 + mt * 16 + (lane >> 2);
#pragma unroll
        for (int nt = 0; nt < 8; nt++) {
            int col = n0 + (nt >> 1) * 16 + (nt & 1) * 8 + (lane & 3) * 2;
            float b0 = __ldg(cv + col);
            float b1 = __ldg(cv + col + 1);
            float2 v0 = make_float2(acc[mt][nt][0] + b0, acc[mt][nt][1] + b1);
            float2 v1 = make_float2(acc[mt][nt][2] + b0, acc[mt][nt][3] + b1);
            size_t base0 = (size_t)r0 * OUTSTRIDE + a * EDIM + col;
            size_t base1 = (size_t)(r0 + 8) * OUTSTRIDE + a * EDIM + col;
            *reinterpret_cast<float2*>(out + base0) = v0;
            *reinterpret_cast<float2*>(out + base1) = v1;
        }
    }
}

extern "C" void kernel_launch(void* const* d_in, const int* in_sizes, int n_in,
                              void* d_out, int out_size) {
    const float* img  = (const float*)d_in[0];   // [B, E]
    const float* edge = (const float*)d_in[1];   // [B, A, E]
    const float* W    = (const float*)d_in[2];   // [E, 2E]
    const float* bvec = (const float*)d_in[3];   // [E]
    const float* proj = (const float*)d_in[4];   // [A, E, E]
    const int Bn = in_sizes[0] / EDIM;

    precompute_kernel<<<dim3(NUM_A, EDIM), EDIM>>>(W, bvec, proj);

    cudaFuncSetAttribute(gnn_kernel, cudaFuncAttributeMaxDynamicSharedMemorySize,
                         NSTAGE * STAGE_BYTES);
    // blockIdx.x = a (fast dim) so the 8 a-CTAs of one m-tile run adjacently:
    // img tile and the contiguous edge row block get full L2 reuse.
    gnn_kernel<<<dim3(NUM_A, Bn / MTILE), THREADS, NSTAGE * STAGE_BYTES>>>(
        img, edge, (float*)d_out);
}

// round 7
// speedup vs baseline: 1.3114x; 1.2490x over previous
#include <cuda_runtime.h>
#include <cuda_fp16.h>
#include <cstdint>

#define NUM_A 8
#define EDIM 128
#define OUTSTRIDE (NUM_A * EDIM)   // 1024 floats per batch row of edge/out
#define KC 32                      // K elements per pipeline chunk
#define NCHUNK 8                   // total K = 256 (128 img + 128 edge)
#define NSTAGE 3
#define MTILE 128
#define THREADS 128                // 4 warps, each owning a 64x64 output tile
#define A_BYTES (MTILE * KC * 4)           // 16 KB fp32 A tile
#define B_BYTES (EDIM * KC * 2)            // 8 KB fp16 B tile (128 j-rows x 64B)
#define STAGE_BYTES (A_BYTES + B_BYTES)    // 24 KB

// Precomputed fused weights in fp16 (n-major rows, k contiguous) + fp32 bias-via-proj.
__device__ __half g_P1h[NUM_A * EDIM * EDIM];  // [a][j][k] = sum_i W[i,k]   * proj[a,i,j]
__device__ __half g_P2h[NUM_A * EDIM * EDIM];  // [a][j][k] = sum_i W[i,E+k] * proj[a,i,j]
__device__ float  g_cvec[NUM_A * EDIM];        // [a][j]    = sum_i b[i]     * proj[a,i,j]

__device__ __forceinline__ uint32_t swz(uint32_t x) { return x ^ ((x >> 3) & 0x70u); }

__device__ __forceinline__ void cp_async16(uint32_t dst, const void* src) {
    asm volatile("cp.async.cg.shared.global [%0], [%1], 16;" :: "r"(dst), "l"(src));
}
__device__ __forceinline__ void cp_commit() { asm volatile("cp.async.commit_group;"); }
template <int N> __device__ __forceinline__ void cp_wait() {
    asm volatile("cp.async.wait_group %0;" :: "n"(N));
}
__device__ __forceinline__ void ldsm_x4(uint32_t& r0, uint32_t& r1, uint32_t& r2, uint32_t& r3,
                                        uint32_t addr) {
    asm volatile("ldmatrix.sync.aligned.m8n8.x4.shared.b16 {%0,%1,%2,%3}, [%4];"
                 : "=r"(r0), "=r"(r1), "=r"(r2), "=r"(r3) : "r"(addr));
}
// pack {lo=f0, hi=f1} into one fp16x2 register
__device__ __forceinline__ uint32_t f16x2(float f0, float f1) {
    uint32_t d;
    asm("cvt.rn.f16x2.f32 %0, %1, %2;" : "=r"(d) : "f"(f1), "f"(f0));
    return d;
}
__device__ __forceinline__ void lds64(float& x, float& y, uint32_t addr) {
    asm volatile("ld.shared.v2.f32 {%0,%1}, [%2];" : "=f"(x), "=f"(y) : "r"(addr));
}
__device__ __forceinline__ void mma_f16(float* c, const uint32_t* a, uint32_t b0, uint32_t b1) {
    asm volatile("mma.sync.aligned.m16n8k16.row.col.f32.f16.f16.f32 "
                 "{%0,%1,%2,%3},{%4,%5,%6,%7},{%8,%9},{%0,%1,%2,%3};"
                 : "+f"(c[0]), "+f"(c[1]), "+f"(c[2]), "+f"(c[3])
                 : "r"(a[0]), "r"(a[1]), "r"(a[2]), "r"(a[3]), "r"(b0), "r"(b1));
}

// B smem swizzle: 64B rows (32 fp16). 16B chunk index gets XORed with (j>>1)&3 so
// the 8 rows of every ldmatrix 8x8 block land on 8 distinct 16B bank groups.
__device__ __forceinline__ uint32_t b_off(int j, int cbyte) {
    return (uint32_t)(j * 64 + ((((cbyte >> 4) ^ ((j >> 1) & 3)) << 4) | (cbyte & 15)));
}

// ---------------------------------------------------------------------------
// Precompute fused weights (fp16) and cvec. 67 MFLOP, negligible.
// ---------------------------------------------------------------------------
__global__ void precompute_kernel(const float* __restrict__ W, const float* __restrict__ bvec,
                                  const float* __restrict__ proj) {
    const int a = blockIdx.x;
    const int j = blockIdx.y;
    const int k = threadIdx.x;
    const float* pa = proj + ((size_t)a * EDIM) * EDIM + j;   // proj[a][i][j], stride E
    float acc1 = 0.f, acc2 = 0.f, accC = 0.f;
#pragma unroll 8
    for (int i = 0; i < EDIM; i++) {
        float p = __ldg(pa + (size_t)i * EDIM);
        acc1 = fmaf(__ldg(W + i * 2 * EDIM + k), p, acc1);
        acc2 = fmaf(__ldg(W + i * 2 * EDIM + EDIM + k), p, acc2);
        accC = fmaf(__ldg(bvec + i), p, accC);
    }
    size_t o = ((size_t)a * EDIM + j) * EDIM + k;
    g_P1h[o] = __float2half_rn(acc1);
    g_P2h[o] = __float2half_rn(acc2);
    if (k == 0) g_cvec[a * EDIM + j] = accC;
}

// ---------------------------------------------------------------------------
// Fused GEMM, fp16 tensor path. CTA = (a, 128-row m-tile), 4 warps x 64x64.
// A fp32 in smem (SW128), fragments built via LDS.64 + cvt.rn.f16x2.
// B fp16 in smem (64B rows, custom swizzle), fragments via ldmatrix.x4.
// mma.sync m16n8k16 f16 (2x MACs/instr vs tf32). 3-stage cp.async pipeline,
// one barrier per chunk, 2 CTAs/SM.
// ---------------------------------------------------------------------------
__global__ __launch_bounds__(THREADS, 2) void gnn_kernel(const float* __restrict__ img,
                                                         const float* __restrict__ edge,
                                                         float* __restrict__ out) {
    extern __shared__ float smem[];
    const uint32_t smem_b = (uint32_t)__cvta_generic_to_shared(smem);
    const int a = blockIdx.x;
    const int mbase = blockIdx.y * MTILE;
    const int tid = threadIdx.x;
    const int lane = tid & 31;
    const int warp = tid >> 5;
    const int m0 = (warp & 1) * 64;    // warp row base within CTA tile
    const int n0 = (warp >> 1) * 64;   // warp col base within CTA tile

    float acc[4][8][4];                // acc[mt][nt], col base = n0 + (nt>>1)*16 + (nt&1)*8
#pragma unroll
    for (int mt = 0; mt < 4; mt++)
#pragma unroll
        for (int nt = 0; nt < 8; nt++)
#pragma unroll
            for (int v = 0; v < 4; v++) acc[mt][nt][v] = 0.f;

    auto load_chunk = [&](int kc, int s) {
        const uint32_t abase = smem_b + s * STAGE_BYTES;
        const uint32_t bbase = abase + A_BYTES;
        const float* srcAbase;
        size_t strideA;
        if (kc < 4) { srcAbase = img + (size_t)mbase * EDIM + kc * KC;                 strideA = EDIM; }
        else        { srcAbase = edge + (size_t)mbase * OUTSTRIDE + a * EDIM + (kc - 4) * KC; strideA = OUTSTRIDE; }
        const __half* Ph = (kc < 4) ? g_P1h : g_P2h;
        const __half* srcBbase = Ph + ((size_t)a * EDIM) * EDIM + (kc & 3) * KC;
        // A: 16KB fp32, SW128 rows of 128B
#pragma unroll
        for (int q = 0; q < 8; q++) {
            int id = tid + q * THREADS;   // 0..1023
            int row = id >> 3;
            int c4 = id & 7;
            cp_async16(abase + swz((uint32_t)(row * 128 + c4 * 16)),
                       srcAbase + (size_t)row * strideA + c4 * 4);
        }
        // B: 8KB fp16, 64B rows with b_off swizzle (512 x 16B)
#pragma unroll
        for (int q = 0; q < 4; q++) {
            int id = tid + q * THREADS;   // 0..511
            int j = id >> 2;
            int c16 = id & 3;
            cp_async16(bbase + b_off(j, c16 * 16), srcBbase + (size_t)j * EDIM + c16 * 8);
        }
        cp_commit();
    };

    auto compute_chunk = [&](int s) {
        const uint32_t abase = smem_b + s * STAGE_BYTES;
        const uint32_t bbase = abase + A_BYTES;
#pragma unroll
        for (int ks = 0; ks < 2; ks++) {   // 2 k16 steps per 32-wide chunk
            // A fragments: fp32 LDS.64 pairs -> fp16x2
            uint32_t afr[4][4];
#pragma unroll
            for (int mt = 0; mt < 4; mt++) {
                int r = m0 + mt * 16 + (lane >> 2);
                uint32_t kb = (uint32_t)(ks * 64 + (lane & 3) * 8);   // byte offset of k pair
                uint32_t ad0 = abase + r * 128 + (kb ^ (uint32_t)((r & 7) << 4));
                uint32_t ad1 = abase + (r + 8) * 128 + (kb ^ (uint32_t)(((r + 8) & 7) << 4));
                float x0, y0, x1, y1, x2, y2, x3, y3;
                lds64(x0, y0, ad0);          // (r,   k..k+1)
                lds64(x1, y1, ad1);          // (r+8, k..k+1)
                lds64(x2, y2, ad0 ^ 32u);    // (r,   k+8..k+9)  (+32B flips bit5; swizzle-safe)
                lds64(x3, y3, ad1 ^ 32u);    // (r+8, k+8..k+9)
                afr[mt][0] = f16x2(x0, y0);
                afr[mt][1] = f16x2(x1, y1);
                afr[mt][2] = f16x2(x2, y2);
                afr[mt][3] = f16x2(x3, y3);
            }
            // B fragments: ldmatrix.x4 per 16-col group
#pragma unroll
            for (int ng = 0; ng < 4; ng++) {
                int blk = lane >> 3;                       // 0..3
                int jr = n0 + ng * 16 + (lane & 7) + ((blk & 2) ? 8 : 0);
                int cB = ks * 32 + (blk & 1) * 16;         // byte offset within row
                uint32_t r0, r1, r2, r3;
                ldsm_x4(r0, r1, r2, r3, bbase + b_off(jr, cB));
#pragma unroll
                for (int mt = 0; mt < 4; mt++) {
                    mma_f16(acc[mt][ng * 2],     afr[mt], r0, r1);
                    mma_f16(acc[mt][ng * 2 + 1], afr[mt], r2, r3);
                }
            }
        }
    };

    // 3-stage pipeline: preload chunks 0,1; each iteration waits for chunk kc,
    // barriers once, issues load kc+2 into the freed stage, computes kc.
    load_chunk(0, 0);
    load_chunk(1, 1);
#pragma unroll 1
    for (int kc = 0; kc < NCHUNK; kc++) {
        if (kc < NCHUNK - 1) { cp_wait<1>(); } else { cp_wait<0>(); }
        __syncthreads();
        if (kc + 2 < NCHUNK) load_chunk(kc + 2, (kc + 2) % NSTAGE);
        compute_chunk(kc % NSTAGE);
    }

    // Epilogue: add bias-through-projection, store float2 pairs.
    const float* cv = g_cvec + a * EDIM;
#pragma unroll
    for (int mt = 0; mt < 4; mt++) {
        int r0 = mbase + m0 + mt * 16 + (lane >> 2);
#pragma unroll
        for (int nt = 0; nt < 8; nt++) {
            int col = n0 + (nt >> 1) * 16 + (nt & 1) * 8 + (lane & 3) * 2;
            float b0 = __ldg(cv + col);
            float b1 = __ldg(cv + col + 1);
            float2 v0 = make_float2(acc[mt][nt][0] + b0, acc[mt][nt][1] + b1);
            float2 v1 = make_float2(acc[mt][nt][2] + b0, acc[mt][nt][3] + b1);
            size_t base0 = (size_t)r0 * OUTSTRIDE + a * EDIM + col;
            size_t base1 = (size_t)(r0 + 8) * OUTSTRIDE + a * EDIM + col;
            *reinterpret_cast<float2*>(out + base0) = v0;
            *reinterpret_cast<float2*>(out + base1) = v1;
        }
    }
}

extern "C" void kernel_launch(void* const* d_in, const int* in_sizes, int n_in,
                              void* d_out, int out_size) {
    const float* img  = (const float*)d_in[0];   // [B, E]
    const float* edge = (const float*)d_in[1];   // [B, A, E]
    const float* W    = (const float*)d_in[2];   // [E, 2E]
    const float* bvec = (const float*)d_in[3];   // [E]
    const float* proj = (const float*)d_in[4];   // [A, E, E]
    const int Bn = in_sizes[0] / EDIM;

    precompute_kernel<<<dim3(NUM_A, EDIM), EDIM>>>(W, bvec, proj);

    cudaFuncSetAttribute(gnn_kernel, cudaFuncAttributeMaxDynamicSharedMemorySize,
                         NSTAGE * STAGE_BYTES);
    // blockIdx.x = a (fast dim) so the 8 a-CTAs of one m-tile run adjacently:
    // img tile and the contiguous edge row block get full L2 reuse.
    gnn_kernel<<<dim3(NUM_A, Bn / MTILE), THREADS, NSTAGE * STAGE_BYTES>>>(
        img, edge, (float*)d_out);
}